// round 1
// baseline (speedup 1.0000x reference)
#include <cuda_runtime.h>
#include <cuda_bf16.h>
#include <math.h>

// Problem constants
#define PH     5
#define NCOIL  16          // ch*d = 8*2
#define NIM    320         // H = W
#define KOS    640         // 2x oversampled grid
#define KLEN   16000
#define JTAPS  6
#define ALPHA_F 14.04f     // 2.34 * 6
#define PI_F   3.14159265358979323846f

// ---------------------------------------------------------------------------
// Static device scratch (no allocations allowed)
// ---------------------------------------------------------------------------
__device__ float2 g_R[PH * NCOIL * NIM * KOS];      // stage-1 result (131 MB)
__device__ float2 g_G[PH * NCOIL * KOS * KOS];      // oversampled spectrum (262 MB)
__device__ float2 g_D[NIM * KOS];                   // DFT matrix e^{-2pi i a b / 640}
__device__ float  g_sh[NIM];                        // apodization (sh == sw)
__device__ float  g_inv_i0a;                        // 1 / I0(alpha)

// ---------------------------------------------------------------------------
// Modified Bessel I0 (Abramowitz & Stegun 9.8.1 / 9.8.2, rel err ~2e-7)
// ---------------------------------------------------------------------------
__device__ __forceinline__ float i0f_dev(float x) {
    if (x < 3.75f) {
        float t = x * (1.0f / 3.75f);
        t *= t;
        return 1.0f + t * (3.5156229f + t * (3.0899424f + t * (1.2067492f +
               t * (0.2659732f + t * (0.0360768f + t * 0.0045813f)))));
    } else {
        float t = 3.75f / x;
        float p = 0.39894228f + t * (0.01328592f + t * (0.00225319f +
                  t * (-0.00157565f + t * (0.00916281f + t * (-0.02057706f +
                  t * (0.02635537f + t * (-0.01647633f + t * 0.00392377f)))))));
        return p * expf(x) * rsqrtf(x);
    }
}

// ---------------------------------------------------------------------------
// Init kernels (cheap, re-run every launch for determinism)
// ---------------------------------------------------------------------------
__global__ void init_scale_kernel() {
    int n = threadIdx.x;                  // 320 threads
    if (n >= NIM) return;
    float i0a = i0f_dev(ALPHA_F);
    if (n == 0) g_inv_i0a = 1.0f / i0a;
    float nn = (float)(n - NIM / 2);
    float u  = nn * (1.0f / (float)KOS);
    float w  = PI_F * (float)JTAPS * u;
    float z2 = w * w - ALPHA_F * ALPHA_F;
    float z  = fmaxf(sqrtf(fabsf(z2)), 1e-6f);
    float core = (z2 > 0.0f) ? (sinf(z) / z) : (sinhf(z) / z);
    float ft = core * ((float)JTAPS / i0a);
    g_sh[n] = 1.0f / ft;
}

__global__ void init_dft_kernel() {
    int idx = blockIdx.x * blockDim.x + threadIdx.x;
    if (idx >= NIM * KOS) return;
    int m = idx / KOS;
    int q = idx - m * KOS;
    int r = (m * q) % KOS;                // exact integer angle reduction
    float s, c;
    sincospif(-(float)r * (1.0f / 320.0f), &s, &c);   // -2*pi*r/640
    g_D[idx] = make_float2(c, s);
}

// ---------------------------------------------------------------------------
// Tiled complex GEMM: C[M,N] = sum_t opA(i,t) * B[t,j]
//   TRANSA=false: opA(i,t) = A[i*lda + t]   (optionally apodized by sh[i]*sh[t])
//   TRANSA=true : opA(i,t) = A[t*lda + i]
// Block tile 64x64, K-tile 16, 256 threads, 4x4 complex accum per thread.
// M, N multiples of 64; K multiple of 16 (true here: 320/640/320).
// ---------------------------------------------------------------------------
#define BM 64
#define BN 64
#define BK 16

template <bool TRANSA, bool APOD>
__global__ __launch_bounds__(256) void cgemm_kernel(
    const float2* __restrict__ A, const float2* __restrict__ B,
    float2* __restrict__ C,
    int lda, int ldb, int ldc, int K,
    long sA, long sB, long sC)
{
    __shared__ float2 As[BK][BM + 2];
    __shared__ float2 Bs[BK][BN + 2];

    const int tid = threadIdx.x;
    const int tx = tid & 15;          // output col group
    const int ty = tid >> 4;          // output row group
    const int j0 = blockIdx.x * BN;
    const int i0 = blockIdx.y * BM;

    const float2* Ab = A + (long)blockIdx.z * sA;
    const float2* Bb = B + (long)blockIdx.z * sB;
    float2*       Cb = C + (long)blockIdx.z * sC;

    float2 acc[4][4];
#pragma unroll
    for (int r = 0; r < 4; r++)
#pragma unroll
        for (int c = 0; c < 4; c++) acc[r][c] = make_float2(0.0f, 0.0f);

    for (int t0 = 0; t0 < K; t0 += BK) {
        // ---- load A tile into As[k][i] ----
#pragma unroll
        for (int r = 0; r < 4; r++) {
            int idx = tid + r * 256;
            if (!TRANSA) {
                int kk = idx & 15;
                int i  = idx >> 4;
                float2 v = Ab[(long)(i0 + i) * lda + (t0 + kk)];
                if (APOD) {
                    float s = g_sh[i0 + i] * g_sh[t0 + kk];
                    v.x *= s; v.y *= s;
                }
                As[kk][i] = v;
            } else {
                int i  = idx & 63;
                int kk = idx >> 6;
                As[kk][i] = Ab[(long)(t0 + kk) * lda + (i0 + i)];
            }
            // ---- load B tile into Bs[k][j] ----
            int j   = idx & 63;
            int kk2 = idx >> 6;
            Bs[kk2][j] = Bb[(long)(t0 + kk2) * ldb + (j0 + j)];
        }
        __syncthreads();

#pragma unroll
        for (int kk = 0; kk < BK; kk++) {
            float2 a[4], b[4];
#pragma unroll
            for (int r = 0; r < 4; r++) a[r] = As[kk][ty * 4 + r];
#pragma unroll
            for (int c = 0; c < 4; c++) b[c] = Bs[kk][tx * 4 + c];
#pragma unroll
            for (int r = 0; r < 4; r++) {
#pragma unroll
                for (int c = 0; c < 4; c++) {
                    // complex FMA: acc += a*b  (4 FFMA)
                    acc[r][c].x = fmaf(a[r].x, b[c].x, acc[r][c].x);
                    acc[r][c].x = fmaf(-a[r].y, b[c].y, acc[r][c].x);
                    acc[r][c].y = fmaf(a[r].x, b[c].y, acc[r][c].y);
                    acc[r][c].y = fmaf(a[r].y, b[c].x, acc[r][c].y);
                }
            }
        }
        __syncthreads();
    }

#pragma unroll
    for (int r = 0; r < 4; r++)
#pragma unroll
        for (int c = 0; c < 4; c++)
            Cb[(long)(i0 + ty * 4 + r) * ldc + (j0 + tx * 4 + c)] = acc[r][c];
}

// ---------------------------------------------------------------------------
// KB interpolation: 6x6 taps per k-space point, 16 coils in parallel.
// Block = 256 threads = 16 points x 16 coils. Grid (KLEN/16, PH).
// ---------------------------------------------------------------------------
__global__ __launch_bounds__(256) void interp_kernel(
    const float* __restrict__ traj, float2* __restrict__ out)
{
    __shared__ float s_wh[16][JTAPS], s_ww[16][JTAPS];
    __shared__ int   s_ih[16][JTAPS], s_iw[16][JTAPS];
    __shared__ float s_pr[16], s_pi[16];

    const int tid = threadIdx.x;
    const int cd  = tid & 15;
    const int li  = tid >> 4;
    const int p   = blockIdx.y;
    const int l   = blockIdx.x * 16 + li;

    const float inv_i0a = g_inv_i0a;

    if (cd < 2) {
        // cd==0 -> row dim (omega[0]); cd==1 -> col dim (omega[1])
        float om = traj[(long)(p * 2 + cd) * KLEN + l];
        float t  = om * (320.0f / PI_F);     // om * K / (2*pi), K=640
        float base = floorf(t - 3.0f);
#pragma unroll
        for (int j = 0; j < JTAPS; j++) {
            float kf  = base + (float)(j + 1);
            float u   = t - kf;
            float ua  = u * (1.0f / 3.0f);   // 2u/J
            float arg = fmaxf(1.0f - ua * ua, 0.0f);
            float w   = i0f_dev(ALPHA_F * sqrtf(arg)) * inv_i0a;
            int ki  = (int)kf;               // exact integer-valued float
            int idx = ki % KOS; if (idx < 0) idx += KOS;
            if (cd == 0) { s_wh[li][j] = w; s_ih[li][j] = idx; }
            else         { s_ww[li][j] = w; s_iw[li][j] = idx; }
        }
        if (cd == 0) {
            float om1 = traj[(long)(p * 2 + 1) * KLEN + l];
            float th  = 160.0f * (om + om1);  // n_shift = im_size//2 = 160
            float sp, cp;
            sincosf(th, &sp, &cp);
            s_pr[li] = cp; s_pi[li] = sp;
        }
    }
    __syncthreads();

    const float2* Gp = g_G + (long)((p * NCOIL + cd) * KOS) * KOS;
    float ar = 0.0f, ai = 0.0f;
#pragma unroll
    for (int j1 = 0; j1 < JTAPS; j1++) {
        const float2* row = Gp + (long)s_ih[li][j1] * KOS;
        float w1 = s_wh[li][j1];
#pragma unroll
        for (int j2 = 0; j2 < JTAPS; j2++) {
            float2 v = row[s_iw[li][j2]];
            float  w = w1 * s_ww[li][j2];
            ar = fmaf(v.x, w, ar);
            ai = fmaf(v.y, w, ai);
        }
    }
    float pr = s_pr[li], pi = s_pi[li];
    const float sc = 1.0f / 640.0f;          // ortho norm 1/sqrt(Kh*Kw)
    float2 o;
    o.x = (ar * pr - ai * pi) * sc;
    o.y = (ar * pi + ai * pr) * sc;
    out[(long)((p * NCOIL + cd) * KLEN + l)] = o;
}

// ---------------------------------------------------------------------------
// Launch
// ---------------------------------------------------------------------------
extern "C" void kernel_launch(void* const* d_in, const int* in_sizes, int n_in,
                              void* d_out, int out_size)
{
    const float2* image = (const float2*)d_in[0];   // (1,5,8,2,320,320,2) -> float2
    const float*  traj  = (const float*)d_in[1];    // (5,2,16000)

    float2 *Rp, *Gp, *Dp;
    cudaGetSymbolAddress((void**)&Rp, g_R);
    cudaGetSymbolAddress((void**)&Gp, g_G);
    cudaGetSymbolAddress((void**)&Dp, g_D);

    init_scale_kernel<<<1, 320>>>();
    init_dft_kernel<<<(NIM * KOS + 255) / 256, 256>>>();

    // Stage 1: R[n,q] = sum_m (x[n,m]*sh[n]*sh[m]) * D[m,q]
    //   A = image (batched, lda=320), B = D (shared, ldb=640)
    {
        dim3 grid(KOS / BN, NIM / BM, PH * NCOIL);    // (10, 5, 80)
        cgemm_kernel<false, true><<<grid, 256>>>(
            image, Dp, Rp,
            NIM, KOS, KOS, NIM,
            (long)NIM * NIM, 0L, (long)NIM * KOS);
    }

    // Stage 2: G[k,q] = sum_n D[n,k] * R[n,q]   (A = D transposed access)
    {
        dim3 grid(KOS / BN, KOS / BM, PH * NCOIL);    // (10, 10, 80)
        cgemm_kernel<true, false><<<grid, 256>>>(
            Dp, Rp, Gp,
            KOS, KOS, KOS, NIM,
            0L, (long)NIM * KOS, (long)KOS * KOS);
    }

    // Stage 3: KB interpolation + recentering phase + ortho scale
    {
        dim3 grid(KLEN / 16, PH);                     // (1000, 5)
        interp_kernel<<<grid, 256>>>(traj, (float2*)d_out);
    }
}

// round 3
// speedup vs baseline: 5.0308x; 5.0308x over previous
#include <cuda_runtime.h>
#include <cuda_bf16.h>
#include <math.h>

// Problem constants
#define PH     5
#define NCOIL  16          // ch*d = 8*2
#define NIM    320         // H = W
#define KOS    640         // 2x oversampled grid
#define KLEN   16000
#define JTAPS  6
#define ALPHA_F 14.04f     // 2.34 * 6
#define PI_F   3.14159265358979323846f

// ---------------------------------------------------------------------------
// Static device scratch (no allocations allowed)
// ---------------------------------------------------------------------------
__device__ float2 g_R[PH * NCOIL * KOS * NIM];      // R_T [b][q<640][n<320] (131 MB)
__device__ float2 g_G[PH * NCOIL * KOS * KOS];      // G   [b][k][q]        (262 MB)
__device__ float  g_sh[NIM];                        // apodization (sh == sw)
__device__ float  g_inv_i0a;                        // 1 / I0(alpha)

// ---------------------------------------------------------------------------
// Modified Bessel I0 (Abramowitz & Stegun 9.8.1 / 9.8.2, rel err ~2e-7)
// ---------------------------------------------------------------------------
__device__ __forceinline__ float i0f_dev(float x) {
    if (x < 3.75f) {
        float t = x * (1.0f / 3.75f);
        t *= t;
        return 1.0f + t * (3.5156229f + t * (3.0899424f + t * (1.2067492f +
               t * (0.2659732f + t * (0.0360768f + t * 0.0045813f)))));
    } else {
        float t = 3.75f / x;
        float p = 0.39894228f + t * (0.01328592f + t * (0.00225319f +
                  t * (-0.00157565f + t * (0.00916281f + t * (-0.02057706f +
                  t * (0.02635537f + t * (-0.01647633f + t * 0.00392377f)))))));
        return p * expf(x) * rsqrtf(x);
    }
}

// ---------------------------------------------------------------------------
// Init: apodization weights
// ---------------------------------------------------------------------------
__global__ void init_scale_kernel() {
    int n = threadIdx.x;                  // 320 threads
    if (n >= NIM) return;
    float i0a = i0f_dev(ALPHA_F);
    if (n == 0) g_inv_i0a = 1.0f / i0a;
    float nn = (float)(n - NIM / 2);
    float u  = nn * (1.0f / (float)KOS);
    float w  = PI_F * (float)JTAPS * u;
    float z2 = w * w - ALPHA_F * ALPHA_F;
    float z  = fmaxf(sqrtf(fabsf(z2)), 1e-6f);
    float core = (z2 > 0.0f) ? (sinf(z) / z) : (sinhf(z) / z);
    float ft = core * ((float)JTAPS / i0a);
    g_sh[n] = 1.0f / ft;
}

// ---------------------------------------------------------------------------
// Four-step 640-pt DFT of a zero-padded length-320 signal.
//   n = 32*n1 + n2 (n1<20, n2<32; nonzero only n1<10),  k = k1 + 20*k2.
//   X[k1+20k2] = sum_{n2} W640^{n2 k1} W32^{n2 k2} * T[n2][k1]
//   T[n2][k1]  = sum_{n1<10} x[32 n1 + n2] W20^{n1 k1}
// One warp per column (lane = n2). Outer 32-DFT done as Horner evaluation
// at w = W32^{k2} with broadcast shared reads.
// Input rows are contiguous length-320; output written transposed+coalesced:
//   out[(b*640 + k)*rows_pb + r_local],  rows_pb = rows per batch.
// ---------------------------------------------------------------------------
template <bool APOD>
__global__ __launch_bounds__(256) void fft640_kernel(
    const float2* __restrict__ in, float2* __restrict__ out, int rows_pb)
{
    __shared__ float2 tw[KOS];           // W640^t
    __shared__ float2 buf[8][KOS + 1];   // per-warp scratch (pad 1 row elem)

    const int tid  = threadIdx.x;
    const int w    = tid >> 5;
    const int lane = tid & 31;

    // exact twiddle table: e^{-2*pi*i*t/640}
    for (int t = tid; t < KOS; t += 256) {
        float s, c;
        sincospif(-(float)t * (1.0f / 320.0f), &s, &c);
        tw[t] = make_float2(c, s);
    }
    __syncthreads();

    const int r_global = blockIdx.x * 8 + w;      // column id
    const int b  = (blockIdx.x * 8) / rows_pb;    // batch (whole block same b)
    const int r0 = (blockIdx.x * 8) % rows_pb;    // first local row in block
    const int rl = r0 + w;                        // this warp's local row

    // ---- load 10 inputs (coalesced: lane = n2) ----
    float2 xv[10];
    const float2* ip = in + (size_t)r_global * NIM + lane;
    float shr = 1.0f;
    if (APOD) shr = g_sh[rl];
#pragma unroll
    for (int n1 = 0; n1 < 10; n1++) {
        float2 v = ip[n1 * 32];
        if (APOD) {
            float s = shr * g_sh[n1 * 32 + lane];
            v.x *= s; v.y *= s;
        }
        xv[n1] = v;
    }

    // ---- phase A: inner 20-pt DFT + W640 twiddle -> S[k1][n2] ----
#pragma unroll
    for (int k1 = 0; k1 < 20; k1++) {
        float2 T = xv[0];                         // W20^0 = 1
#pragma unroll
        for (int n1 = 1; n1 < 10; n1++) {
            const int jj = (n1 * k1) % 20;        // compile-time after unroll
            float2 c = tw[jj * 32];               // W20^jj = W640^{32 jj}
            T.x = fmaf(xv[n1].x, c.x, T.x);
            T.x = fmaf(-xv[n1].y, c.y, T.x);
            T.y = fmaf(xv[n1].x, c.y, T.y);
            T.y = fmaf(xv[n1].y, c.x, T.y);
        }
        float2 t6 = tw[lane * k1];                // W640^{n2 k1}, idx <= 589
        float2 S;
        S.x = T.x * t6.x - T.y * t6.y;
        S.y = T.x * t6.y + T.y * t6.x;
        buf[w][k1 * 32 + lane] = S;
    }
    __syncwarp();

    // ---- phase B: outer 32-pt DFT via Horner at w_h = W32^{k2=lane} ----
    const float2 wh = tw[20 * lane];
    float2 Y[20];
#pragma unroll 2
    for (int k1 = 0; k1 < 20; k1++) {
        const float2* Sp = &buf[w][k1 * 32];
        float2 y = Sp[31];
#pragma unroll
        for (int n2 = 30; n2 >= 0; n2--) {
            float2 s = Sp[n2];                    // broadcast read
            float t = fmaf(y.x, wh.x, fmaf(-y.y, wh.y, s.x));
            y.y     = fmaf(y.x, wh.y, fmaf( y.y, wh.x, s.y));
            y.x = t;
        }
        Y[k1] = y;
    }
    __syncwarp();

    // ---- phase C: scatter Y into buf[w][q], q = k1 + 20*k2 ----
#pragma unroll
    for (int k1 = 0; k1 < 20; k1++)
        buf[w][k1 + 20 * lane] = Y[k1];
    __syncthreads();

    // ---- phase D: coalesced transposed global store ----
#pragma unroll
    for (int i = 0; i < 20; i++) {
        int idx = i * 256 + tid;                  // 0 .. 5119
        int q  = idx >> 3;
        int nn = idx & 7;
        out[((size_t)b * KOS + q) * rows_pb + r0 + nn] = buf[nn][q];
    }
}

// ---------------------------------------------------------------------------
// KB interpolation: 6x6 taps per k-space point, 16 coils in parallel.
// Block = 256 threads = 16 points x 16 coils. Grid (KLEN/16, PH).
// ---------------------------------------------------------------------------
__global__ __launch_bounds__(256) void interp_kernel(
    const float* __restrict__ traj, float2* __restrict__ out)
{
    __shared__ float s_wh[16][JTAPS], s_ww[16][JTAPS];
    __shared__ int   s_ih[16][JTAPS], s_iw[16][JTAPS];
    __shared__ float s_pr[16], s_pi[16];

    const int tid = threadIdx.x;
    const int cd  = tid & 15;
    const int li  = tid >> 4;
    const int p   = blockIdx.y;
    const int l   = blockIdx.x * 16 + li;

    const float inv_i0a = g_inv_i0a;

    if (cd < 2) {
        float om = traj[(long)(p * 2 + cd) * KLEN + l];
        float t  = om * (320.0f / PI_F);     // om * K / (2*pi), K=640
        float base = floorf(t - 3.0f);
#pragma unroll
        for (int j = 0; j < JTAPS; j++) {
            float kf  = base + (float)(j + 1);
            float u   = t - kf;
            float ua  = u * (1.0f / 3.0f);   // 2u/J
            float arg = fmaxf(1.0f - ua * ua, 0.0f);
            float w   = i0f_dev(ALPHA_F * sqrtf(arg)) * inv_i0a;
            int ki  = (int)kf;
            int idx = ki % KOS; if (idx < 0) idx += KOS;
            if (cd == 0) { s_wh[li][j] = w; s_ih[li][j] = idx; }
            else         { s_ww[li][j] = w; s_iw[li][j] = idx; }
        }
        if (cd == 0) {
            float om1 = traj[(long)(p * 2 + 1) * KLEN + l];
            float th  = 160.0f * (om + om1);  // n_shift = im_size//2 = 160
            float sp, cp;
            sincosf(th, &sp, &cp);
            s_pr[li] = cp; s_pi[li] = sp;
        }
    }
    __syncthreads();

    const float2* Gp = g_G + (long)((p * NCOIL + cd) * KOS) * KOS;
    float ar = 0.0f, ai = 0.0f;
#pragma unroll
    for (int j1 = 0; j1 < JTAPS; j1++) {
        const float2* row = Gp + (long)s_ih[li][j1] * KOS;
        float w1 = s_wh[li][j1];
#pragma unroll
        for (int j2 = 0; j2 < JTAPS; j2++) {
            float2 v = row[s_iw[li][j2]];
            float  w = w1 * s_ww[li][j2];
            ar = fmaf(v.x, w, ar);
            ai = fmaf(v.y, w, ai);
        }
    }
    float pr = s_pr[li], pi = s_pi[li];
    const float sc = 1.0f / 640.0f;          // ortho norm 1/sqrt(Kh*Kw)
    float2 o;
    o.x = (ar * pr - ai * pi) * sc;
    o.y = (ar * pi + ai * pr) * sc;
    out[(long)((p * NCOIL + cd) * KLEN + l)] = o;
}

// ---------------------------------------------------------------------------
// Launch
// ---------------------------------------------------------------------------
extern "C" void kernel_launch(void* const* d_in, const int* in_sizes, int n_in,
                              void* d_out, int out_size)
{
    const float2* image = (const float2*)d_in[0];   // (1,5,8,2,320,320,2)
    const float*  traj  = (const float*)d_in[1];    // (5,2,16000)

    float2 *Rp, *Gp;
    cudaGetSymbolAddress((void**)&Rp, g_R);
    cudaGetSymbolAddress((void**)&Gp, g_G);

    init_scale_kernel<<<1, 320>>>();

    // Stage 1: FFT along m (width) with apodization.
    //   columns = 80 batches * 320 rows = 25600 -> R_T[b][q][n]
    fft640_kernel<true><<<(PH * NCOIL * NIM) / 8, 256>>>(image, Rp, NIM);

    // Stage 2: FFT along n (height).
    //   columns = 80 batches * 640 q's = 51200 -> G[b][k][q]
    fft640_kernel<false><<<(PH * NCOIL * KOS) / 8, 256>>>(Rp, Gp, KOS);

    // Stage 3: KB interpolation + recentering phase + ortho scale
    {
        dim3 grid(KLEN / 16, PH);                     // (1000, 5)
        interp_kernel<<<grid, 256>>>(traj, (float2*)d_out);
    }
}

// round 4
// speedup vs baseline: 7.9762x; 1.5855x over previous
#include <cuda_runtime.h>
#include <cuda_bf16.h>
#include <math.h>

// Problem constants
#define PH     5
#define NCOIL  16          // ch*d = 8*2
#define NIM    320         // H = W
#define KOS    640         // 2x oversampled grid
#define KLEN   16000
#define JTAPS  6
#define ALPHA_F 14.04f     // 2.34 * 6
#define PI_F   3.14159265358979323846f

// ---------------------------------------------------------------------------
// Static device scratch (no allocations allowed)
//   g_R: stage-1 out, layout [p][q][c][n]   (p<5, q<640, c<16, n<320)
//   g_G: stage-2 out, layout [p][k][q][c]   (coil innermost for interp)
// ---------------------------------------------------------------------------
__device__ float2 g_R[PH * KOS * NCOIL * NIM];      // 131 MB
__device__ float2 g_G[PH * KOS * KOS * NCOIL];      // 262 MB
__device__ float  g_sh[NIM];                        // apodization (sh == sw)
__device__ float  g_inv_i0a;                        // 1 / I0(alpha)

// ---------------------------------------------------------------------------
// Modified Bessel I0 (Abramowitz & Stegun 9.8.1 / 9.8.2, rel err ~2e-7)
// ---------------------------------------------------------------------------
__device__ __forceinline__ float i0f_dev(float x) {
    if (x < 3.75f) {
        float t = x * (1.0f / 3.75f);
        t *= t;
        return 1.0f + t * (3.5156229f + t * (3.0899424f + t * (1.2067492f +
               t * (0.2659732f + t * (0.0360768f + t * 0.0045813f)))));
    } else {
        float t = 3.75f / x;
        float p = 0.39894228f + t * (0.01328592f + t * (0.00225319f +
                  t * (-0.00157565f + t * (0.00916281f + t * (-0.02057706f +
                  t * (0.02635537f + t * (-0.01647633f + t * 0.00392377f)))))));
        return p * expf(x) * rsqrtf(x);
    }
}

__global__ void init_scale_kernel() {
    int n = threadIdx.x;
    if (n >= NIM) return;
    float i0a = i0f_dev(ALPHA_F);
    if (n == 0) g_inv_i0a = 1.0f / i0a;
    float nn = (float)(n - NIM / 2);
    float u  = nn * (1.0f / (float)KOS);
    float w  = PI_F * (float)JTAPS * u;
    float z2 = w * w - ALPHA_F * ALPHA_F;
    float z  = fmaxf(sqrtf(fabsf(z2)), 1e-6f);
    float core = (z2 > 0.0f) ? (sinf(z) / z) : (sinhf(z) / z);
    float ft = core * ((float)JTAPS / i0a);
    g_sh[n] = 1.0f / ft;
}

// ---------------------------------------------------------------------------
// Four-step 640-pt DFT of a zero-padded length-320 signal, one warp/column.
//   n = 32*n1 + n2 (n1<20, n2=lane<32; nonzero n1<10),  k = k1 + 20*k2.
// Phase A: 20-pt DFT over n1 via even/odd split into two 5-in 10-pt DFTs.
// Phase B: 32-pt DFT over lanes via radix-4 split: lane computes one 8-term
//          Horner P_s[k2&7], then 4x shfl + 3 twiddled combines.
// MODE 1: stage-1 (apodized, image -> R[p][q][c][n])
// MODE 2: stage-2 (R -> G[p][k][q][c])
// Input columns are contiguous length-320 rows at in + col*320.
// ---------------------------------------------------------------------------
template <int MODE>
__global__ __launch_bounds__(256) void fft640_kernel(
    const float2* __restrict__ in, float2* __restrict__ out)
{
    __shared__ float2 tw[KOS];           // tw[t] = e^{-2 pi i t / 640}
    __shared__ float2 buf[8][KOS + 1];   // per-warp scratch

    const int tid  = threadIdx.x;
    const int w    = tid >> 5;
    const int lane = tid & 31;

    for (int t = tid; t < KOS; t += 256) {
        float s, c;
        sincospif(-(float)t * (1.0f / 320.0f), &s, &c);
        tw[t] = make_float2(c, s);
    }
    __syncthreads();

    const int base_col = blockIdx.x * 8;          // 8 columns per block
    const int col = base_col + w;

    // ---- load 10 inputs (coalesced: lane = n2) ----
    float2 xv[10];
    const float2* ip = in + (size_t)col * NIM + lane;
    float shr = 1.0f;
    if (MODE == 1) shr = g_sh[col % NIM];         // row apod weight
#pragma unroll
    for (int n1 = 0; n1 < 10; n1++) {
        float2 v = ip[n1 * 32];
        if (MODE == 1) {
            float s = shr * g_sh[n1 * 32 + lane];
            v.x *= s; v.y *= s;
        }
        xv[n1] = v;
    }

    // ---- phase A: T[k1] = E[k1%10] + W20^k1 * O[k1%10], then W640^{n2 k1} ----
    float2 E[10], O[10];
#pragma unroll
    for (int j = 0; j < 10; j++) {
        float2 e = xv[0], o = xv[1];
#pragma unroll
        for (int m = 1; m < 5; m++) {
            const int jj = (m * j) % 10;          // compile-time
            float2 c = tw[jj * 64];               // W10^jj
            e.x = fmaf(xv[2*m].x,  c.x, e.x); e.x = fmaf(-xv[2*m].y,  c.y, e.x);
            e.y = fmaf(xv[2*m].x,  c.y, e.y); e.y = fmaf( xv[2*m].y,  c.x, e.y);
            o.x = fmaf(xv[2*m+1].x, c.x, o.x); o.x = fmaf(-xv[2*m+1].y, c.y, o.x);
            o.y = fmaf(xv[2*m+1].x, c.y, o.y); o.y = fmaf( xv[2*m+1].y, c.x, o.y);
        }
        E[j] = e; O[j] = o;
    }
#pragma unroll
    for (int k1 = 0; k1 < 20; k1++) {
        const int j = k1 % 10;                    // compile-time
        float2 w20 = tw[32 * k1];                 // W20^k1
        float2 T;
        T.x = fmaf(w20.x, O[j].x, E[j].x); T.x = fmaf(-w20.y, O[j].y, T.x);
        T.y = fmaf(w20.x, O[j].y, E[j].y); T.y = fmaf( w20.y, O[j].x, T.y);
        float2 t6 = tw[lane * k1];                // W640^{n2 k1}, idx <= 589
        float2 S;
        S.x = T.x * t6.x - T.y * t6.y;
        S.y = T.x * t6.y + T.y * t6.x;
        buf[w][k1 * 32 + lane] = S;
    }
    __syncwarp();

    // ---- phase B: 32-pt DFT across lanes, radix-4 split ----
    const int g  = lane >> 3;                     // sub-sequence this lane computes
    const int jj = lane & 7;                      // k2 mod 8
    const float2 w8 = tw[80 * jj];                // W8^jj
    const float2 w1 = tw[20 * lane];              // W32^k2
    const float2 w2 = tw[(40 * lane) % KOS];      // W32^{2 k2}
    const float2 w3 = tw[(60 * lane) % KOS];      // W32^{3 k2}

    float2 Y[20];
#pragma unroll 2
    for (int k1 = 0; k1 < 20; k1++) {
        const float2* Sp = &buf[w][k1 * 32];
        // P_g[jj] = sum_{m<8} S[4m+g] * W8^{m jj}  (Horner)
        float2 P = Sp[28 + g];
#pragma unroll
        for (int m = 6; m >= 0; m--) {
            float2 s = Sp[4 * m + g];
            float t = fmaf(P.x, w8.x, fmaf(-P.y, w8.y, s.x));
            P.y     = fmaf(P.x, w8.y, fmaf( P.y, w8.x, s.y));
            P.x = t;
        }
        // gather P_s for s=0..3 from lanes (s<<3)|jj
        float p0x = __shfl_sync(0xffffffffu, P.x, jj);
        float p0y = __shfl_sync(0xffffffffu, P.y, jj);
        float p1x = __shfl_sync(0xffffffffu, P.x, 8  | jj);
        float p1y = __shfl_sync(0xffffffffu, P.y, 8  | jj);
        float p2x = __shfl_sync(0xffffffffu, P.x, 16 | jj);
        float p2y = __shfl_sync(0xffffffffu, P.y, 16 | jj);
        float p3x = __shfl_sync(0xffffffffu, P.x, 24 | jj);
        float p3y = __shfl_sync(0xffffffffu, P.y, 24 | jj);
        // Y = P0 + w1*P1 + w2*P2 + w3*P3
        float yx = p0x, yy = p0y;
        yx = fmaf(w1.x, p1x, yx); yx = fmaf(-w1.y, p1y, yx);
        yy = fmaf(w1.x, p1y, yy); yy = fmaf( w1.y, p1x, yy);
        yx = fmaf(w2.x, p2x, yx); yx = fmaf(-w2.y, p2y, yx);
        yy = fmaf(w2.x, p2y, yy); yy = fmaf( w2.y, p2x, yy);
        yx = fmaf(w3.x, p3x, yx); yx = fmaf(-w3.y, p3y, yx);
        yy = fmaf(w3.x, p3y, yy); yy = fmaf( w3.y, p3x, yy);
        Y[k1] = make_float2(yx, yy);
    }
    __syncwarp();

    // ---- phase C: scatter Y into buf[w][q], q = k1 + 20*k2 ----
#pragma unroll
    for (int k1 = 0; k1 < 20; k1++)
        buf[w][k1 + 20 * lane] = Y[k1];
    __syncthreads();

    // ---- phase D: coalesced global store (64B contiguous chunks) ----
    size_t out_base; int stride_q;
    if (MODE == 1) {
        // col = (p*16 + c)*320 + n ; out[((p*640+q)*16 + c)*320 + n]
        int pc = base_col / NIM, n0 = base_col % NIM;
        int p = pc >> 4, c = pc & 15;
        out_base = (size_t)p * (640u * 16u * 320u) + (size_t)c * 320u + n0;
        stride_q = 16 * 320;
    } else {
        // col = (p*640 + q)*16 + c ; out[((p*640+k)*640 + q)*16 + c]
        int c0 = base_col & 15;
        int pq = base_col >> 4;
        int q = pq % KOS, p = pq / KOS;
        out_base = (size_t)p * (640u * 640u * 16u) + (size_t)q * 16u + c0;
        stride_q = 640 * 16;
    }
#pragma unroll
    for (int i = 0; i < 20; i++) {
        int idx = i * 256 + tid;                  // 0 .. 5119
        int q  = idx >> 3;                        // FFT output index
        int nn = idx & 7;                         // column within block
        out[out_base + (size_t)q * stride_q + nn] = buf[nn][q];
    }
}

// ---------------------------------------------------------------------------
// KB interpolation: 6x6 taps, 16 coils per point; G is coil-innermost so the
// 16 coil-lanes read 128B contiguous per tap.
// Block = 256 threads = 16 points x 16 coils. Grid (KLEN/16, PH).
// ---------------------------------------------------------------------------
__global__ __launch_bounds__(256) void interp_kernel(
    const float* __restrict__ traj, float2* __restrict__ out)
{
    __shared__ float s_wh[16][JTAPS], s_ww[16][JTAPS];
    __shared__ int   s_ih[16][JTAPS], s_iw[16][JTAPS];
    __shared__ float s_pr[16], s_pi[16];

    const int tid = threadIdx.x;
    const int cd  = tid & 15;                     // coil
    const int li  = tid >> 4;                     // point within block
    const int p   = blockIdx.y;
    const int l   = blockIdx.x * 16 + li;

    const float inv_i0a = g_inv_i0a;

    if (cd < 2) {
        float om = traj[(long)(p * 2 + cd) * KLEN + l];
        float t  = om * (320.0f / PI_F);
        float base = floorf(t - 3.0f);
#pragma unroll
        for (int j = 0; j < JTAPS; j++) {
            float kf  = base + (float)(j + 1);
            float u   = t - kf;
            float ua  = u * (1.0f / 3.0f);
            float arg = fmaxf(1.0f - ua * ua, 0.0f);
            float w   = i0f_dev(ALPHA_F * sqrtf(arg)) * inv_i0a;
            int ki  = (int)kf;
            int idx = ki % KOS; if (idx < 0) idx += KOS;
            if (cd == 0) { s_wh[li][j] = w; s_ih[li][j] = idx; }
            else         { s_ww[li][j] = w; s_iw[li][j] = idx; }
        }
        if (cd == 0) {
            float om1 = traj[(long)(p * 2 + 1) * KLEN + l];
            float th  = 160.0f * (om + om1);
            float sp, cp;
            sincosf(th, &sp, &cp);
            s_pr[li] = cp; s_pi[li] = sp;
        }
    }
    __syncthreads();

    const float2* Gp = g_G + (size_t)p * (640u * 640u * 16u) + cd;
    float ar = 0.0f, ai = 0.0f;
#pragma unroll
    for (int j1 = 0; j1 < JTAPS; j1++) {
        const float2* row = Gp + (size_t)s_ih[li][j1] * (640u * 16u);
        float w1 = s_wh[li][j1];
#pragma unroll
        for (int j2 = 0; j2 < JTAPS; j2++) {
            float2 v = row[s_iw[li][j2] * 16];
            float  w = w1 * s_ww[li][j2];
            ar = fmaf(v.x, w, ar);
            ai = fmaf(v.y, w, ai);
        }
    }
    float pr = s_pr[li], pi = s_pi[li];
    const float sc = 1.0f / 640.0f;               // ortho norm
    float2 o;
    o.x = (ar * pr - ai * pi) * sc;
    o.y = (ar * pi + ai * pr) * sc;
    out[(long)((p * NCOIL + cd) * KLEN) + l] = o;
}

// ---------------------------------------------------------------------------
// Launch
// ---------------------------------------------------------------------------
extern "C" void kernel_launch(void* const* d_in, const int* in_sizes, int n_in,
                              void* d_out, int out_size)
{
    const float2* image = (const float2*)d_in[0];   // (1,5,8,2,320,320,2)
    const float*  traj  = (const float*)d_in[1];    // (5,2,16000)

    float2 *Rp, *Gp;
    cudaGetSymbolAddress((void**)&Rp, g_R);
    cudaGetSymbolAddress((void**)&Gp, g_G);

    init_scale_kernel<<<1, 320>>>();

    // Stage 1: FFT along m (width), apodized.  cols = (p,c,n): 25600
    fft640_kernel<1><<<(PH * NCOIL * NIM) / 8, 256>>>(image, Rp);

    // Stage 2: FFT along n (height).  cols = (p,q,c): 51200
    fft640_kernel<2><<<(PH * KOS * NCOIL) / 8, 256>>>(Rp, Gp);

    // Stage 3: KB interpolation + recentering phase + ortho scale
    {
        dim3 grid(KLEN / 16, PH);
        interp_kernel<<<grid, 256>>>(traj, (float2*)d_out);
    }
}